// round 9
// baseline (speedup 1.0000x reference)
#include <cuda_runtime.h>
#include <cstdint>

// Top-64 per row with ReLU, zeros elsewhere. Two kernels to keep DRAM streams
// unidirectional:
//   K1: pure zero-fill of out (store-only grid-stride sweep, ~full write BW).
//   K2: pure read pass per row: collect x>2.0 candidates into SMEM, exact
//       64th-largest via 8-bit radix select over candidates, scatter the <=64
//       winners (ReLU'd) onto the zeroed output. Ties -> lowest index
//       (jax.lax.top_k semantics). Rare fallbacks keep full generality.

constexpr int NCOLS    = 24576;
constexpr int NT       = 512;              // 16 warps
constexpr int NW       = NT / 32;
constexpr int KSEL     = 64;
constexpr int VEC_IT   = NCOLS / (NT * 4); // 12 float4 per thread
constexpr int CAND_MAX = 2048;
constexpr int MAX_EQ   = 128;
constexpr float TCAND  = 2.0f;

constexpr int SMEM_WORDS = 256 + 32 + 4 + 4 + NW + CAND_MAX + CAND_MAX + MAX_EQ;
constexpr int SMEM_BYTES = SMEM_WORDS * 4;

// zero-fill launch shape: fill the chip once, grid-stride
constexpr int ZNT   = 256;
constexpr int ZGRID = 148 * 8;

__device__ __forceinline__ uint32_t key_of(uint32_t b) {
    uint32_t mask = (uint32_t)((int32_t)b >> 31) | 0x80000000u;
    return b ^ mask;  // larger float <=> larger unsigned key
}
__device__ __forceinline__ float relu_of_key(uint32_t k) {
    return (k & 0x80000000u) ? __uint_as_float(k ^ 0x80000000u) : 0.0f;
}

// ---------------- kernel 1: store-only zero sweep (grid-stride) ----------------
__global__ __launch_bounds__(ZNT)
void zero_kernel(float4* __restrict__ out, int n4) {
    const float4 z4 = make_float4(0.f, 0.f, 0.f, 0.f);
    int stride = gridDim.x * blockDim.x;
    for (int i = blockIdx.x * blockDim.x + threadIdx.x; i < n4; i += stride)
        __stcs(out + i, z4);
}

// suffix-select over nbins (<=256): thread t holds count v of bin t. Finds bin
// where suffix count crosses rank Kre. Writes sel={bin, strictly_above, count}.
__device__ __forceinline__ void suffix_select(
    uint32_t v, uint32_t* scanb, uint32_t* sel,
    int nbins, uint32_t Kre, int t, int lane, int wid)
{
    uint32_t s = v;  // inclusive suffix within warp
    #pragma unroll
    for (int off = 1; off < 32; off <<= 1) {
        uint32_t u = __shfl_down_sync(0xFFFFFFFFu, s, off);
        if (lane + off < 32) s += u;
    }
    const int nw = (nbins + 31) >> 5;
    if (lane == 0 && wid < nw) scanb[wid] = s;
    __syncthreads();
    if (t < 32) {
        uint32_t w = (t < nw) ? scanb[t] : 0u;
        uint32_t ws = w;
        #pragma unroll
        for (int off = 1; off < 32; off <<= 1) {
            uint32_t u = __shfl_down_sync(0xFFFFFFFFu, ws, off);
            if (t + off < 32) ws += u;
        }
        if (t < nw) scanb[t] = ws - w;   // exclusive suffix over warps above
    }
    __syncthreads();
    if (t < nbins) {
        uint32_t above = (s - v) + scanb[wid];
        if (above < Kre && above + v >= Kre) {
            sel[0] = (uint32_t)t; sel[1] = above; sel[2] = v;
        }
    }
    __syncthreads();
}

// ---------------- kernel 2: read-only select + sparse scatter ----------------
__global__ __launch_bounds__(NT, 4)
void topk_relu_kernel(const float* __restrict__ x, float* __restrict__ out) {
    extern __shared__ uint32_t smem[];
    uint32_t* hist  = smem;              // [256]
    uint32_t* scanb = hist + 256;        // [32]
    uint32_t* sel   = scanb + 32;        // [4]
    uint32_t* cnt   = sel + 4;           // [0]=cand, [1]=eq, [2]=npos
    uint32_t* wred  = cnt + 4;           // [NW]
    uint32_t* ck    = wred + NW;         // [CAND_MAX] candidate keys
    uint32_t* ci    = ck + CAND_MAX;     // [CAND_MAX] candidate indices
    uint32_t* eqi   = ci + CAND_MAX;     // [MAX_EQ]

    const int row  = blockIdx.x;
    const int t    = threadIdx.x;
    const int lane = t & 31;
    const int wid  = t >> 5;
    const float4* __restrict__ xv =
        reinterpret_cast<const float4*>(x + (size_t)row * NCOLS);
    float* __restrict__ orow = out + (size_t)row * NCOLS;

    if (t == 0) { cnt[0] = 0; cnt[1] = 0; }
    __syncthreads();

    // ---- read-only pass: collect candidates ----
    #pragma unroll 4
    for (int it = 0; it < VEC_IT; it++) {
        int vi = it * NT + t;
        float4 v = __ldcs(xv + vi);
        float vmax = fmaxf(fmaxf(v.x, v.y), fmaxf(v.z, v.w));
        if (vmax > TCAND) {                 // ~9% of iterations
            int base = vi * 4;
            if (v.x > TCAND) { uint32_t p = atomicAdd(&cnt[0], 1u);
                if (p < CAND_MAX) { ck[p] = __float_as_uint(v.x) | 0x80000000u; ci[p] = base; } }
            if (v.y > TCAND) { uint32_t p = atomicAdd(&cnt[0], 1u);
                if (p < CAND_MAX) { ck[p] = __float_as_uint(v.y) | 0x80000000u; ci[p] = base + 1; } }
            if (v.z > TCAND) { uint32_t p = atomicAdd(&cnt[0], 1u);
                if (p < CAND_MAX) { ck[p] = __float_as_uint(v.z) | 0x80000000u; ci[p] = base + 2; } }
            if (v.w > TCAND) { uint32_t p = atomicAdd(&cnt[0], 1u);
                if (p < CAND_MAX) { ck[p] = __float_as_uint(v.w) | 0x80000000u; ci[p] = base + 3; } }
        }
    }
    __syncthreads();

    const uint32_t ncand = cnt[0];

    uint32_t Pc, Rr, nc;
    int shc;
    if (ncand >= KSEL && ncand <= CAND_MAX) {
        // ---- fast path: candidate set complete and contains the top-64 ----
        Pc = 0; shc = 32; Rr = KSEL; nc = ncand;
    } else {
        // ---- rare paths: need the positive count ----
        uint32_t c0 = 0;
        #pragma unroll 4
        for (int it = 0; it < VEC_IT; it++) {
            float4 v = __ldcs(xv + it * NT + t);
            c0 += (v.x > 0.0f) + (v.y > 0.0f) + (v.z > 0.0f) + (v.w > 0.0f);
        }
        #pragma unroll
        for (int off = 16; off > 0; off >>= 1)
            c0 += __shfl_down_sync(0xFFFFFFFFu, c0, off);
        if (lane == 0) wred[wid] = c0;
        __syncthreads();
        if (t == 0) {
            uint32_t s = 0;
            #pragma unroll
            for (int w = 0; w < NW; w++) s += wred[w];
            cnt[2] = s;
        }
        __syncthreads();
        const uint32_t npos = cnt[2];

        if (npos < KSEL) {
            // 64th largest <= 0: output is exactly relu(x) (over pre-zeroed out)
            #pragma unroll 4
            for (int it = 0; it < VEC_IT; it++) {
                int vi = it * NT + t;
                float4 v = __ldcs(xv + vi);
                v.x = fmaxf(v.x, 0.0f); v.y = fmaxf(v.y, 0.0f);
                v.z = fmaxf(v.z, 0.0f); v.w = fmaxf(v.w, 0.0f);
                __stcs(reinterpret_cast<float4*>(orow) + vi, v);
            }
            return;
        }

        // generic fallback: key-space radix refine (any distribution)
        const uint32_t* xb = reinterpret_cast<const uint32_t*>(x) + (size_t)row * NCOLS;
        uint32_t P = 0, R = KSEL, bc = NCOLS;
        int sh = 32;
        while (bc > CAND_MAX && sh > 0) {
            int nsh = (sh >= 8) ? sh - 8 : 0;
            int nb  = 1 << (sh - nsh);
            for (int i = t; i < nb; i += NT) hist[i] = 0;
            __syncthreads();
            for (int i = t; i < NCOLS; i += NT) {
                uint32_t k = key_of(xb[i]);
                if (sh == 32 || (k >> sh) == P)
                    atomicAdd(&hist[(k >> nsh) & (nb - 1)], 1u);
            }
            __syncthreads();
            uint32_t hv = (t < nb) ? hist[t] : 0u;
            suffix_select(hv, scanb, sel, nb, R, t, lane, wid);
            P  = ((sh == 32) ? 0u : (P << (sh - nsh))) | sel[0];
            R -= sel[1];
            bc = sel[2];
            sh = nsh;
            __syncthreads();
        }
        const uint32_t kLo = (sh == 32) ? 0u : (P << sh);
        const uint32_t kHi = (sh == 32) ? 0xFFFFFFFFu
                             : (uint32_t)(((((uint64_t)P) + 1ull) << sh) - 1ull);
        if (t == 0) cnt[0] = 0;
        __syncthreads();
        for (int i = t; i < NCOLS; i += NT) {
            uint32_t k = key_of(xb[i]);
            if (k > kHi) {
                orow[i] = relu_of_key(k);       // definitely top-64
            } else if (k >= kLo) {
                uint32_t p = atomicAdd(&cnt[0], 1u);
                if (p < CAND_MAX) { ck[p] = k; ci[p] = (uint32_t)i; }
            }
        }
        __syncthreads();
        nc = cnt[0]; if (nc > CAND_MAX) nc = CAND_MAX;
        Pc = P; shc = sh; Rr = R;
    }

    // ---- exact threshold: 8-bit radix select over candidates ----
    while (shc > 0) {
        int nsh = (shc >= 8) ? shc - 8 : 0;
        int nb  = 1 << (shc - nsh);
        for (int i = t; i < nb; i += NT) hist[i] = 0;
        __syncthreads();
        for (uint32_t i = t; i < nc; i += NT) {
            uint32_t k = ck[i];
            if (shc == 32 || (k >> shc) == Pc)
                atomicAdd(&hist[(k >> nsh) & (nb - 1)], 1u);
        }
        __syncthreads();
        uint32_t hv = (t < nb) ? hist[t] : 0u;
        suffix_select(hv, scanb, sel, nb, Rr, t, lane, wid);
        Pc  = ((shc == 32) ? 0u : (Pc << (shc - nsh))) | sel[0];
        Rr -= sel[1];
        shc = nsh;
        __syncthreads();
    }
    const uint32_t Tkey   = Pc;
    const uint32_t keepEq = Rr;                 // # threshold-equal keys to keep
    const float    tval   = relu_of_key(Tkey);

    // ---- scatter strictly-above candidates; collect exact ties ----
    for (uint32_t i = t; i < nc; i += NT) {
        uint32_t k = ck[i];
        if (k > Tkey) {
            orow[ci[i]] = relu_of_key(k);
        } else if (k == Tkey) {
            uint32_t p = atomicAdd(&cnt[1], 1u);
            if (p < MAX_EQ) eqi[p] = ci[i];
        }
    }
    __syncthreads();

    // ---- ties: keep the keepEq equal-keys with smallest indices ----
    uint32_t ne = cnt[1];
    if (ne > MAX_EQ) ne = MAX_EQ;
    if (ne <= keepEq) {
        for (uint32_t e = t; e < ne; e += NT) orow[eqi[e]] = tval;
    } else {
        for (uint32_t e = t; e < ne; e += NT) {
            uint32_t idx = eqi[e];
            uint32_t c = 0;
            for (uint32_t j = 0; j < ne; j++) c += (eqi[j] < idx);
            if (c < keepEq) orow[idx] = tval;
        }
    }
}

extern "C" void kernel_launch(void* const* d_in, const int* in_sizes, int n_in,
                              void* d_out, int out_size) {
    const float* x = (const float*)d_in[0];
    float* out = (float*)d_out;
    const int rows = in_sizes[0] / NCOLS;

    // K1: pure write stream (zero the output)
    int n4 = (rows * NCOLS) / 4;
    zero_kernel<<<ZGRID, ZNT>>>(reinterpret_cast<float4*>(out), n4);

    // K2: pure read stream + sparse scatter
    cudaFuncSetAttribute(topk_relu_kernel,
                         cudaFuncAttributeMaxDynamicSharedMemorySize, SMEM_BYTES);
    topk_relu_kernel<<<rows, NT, SMEM_BYTES>>>(x, out);
}

// round 10
// speedup vs baseline: 1.2327x; 1.2327x over previous
#include <cuda_runtime.h>
#include <cstdint>

// Top-64 per row with ReLU, zeros elsewhere. One CTA per row, SINGLE fused
// data pass (read + zero-store + candidate collection). Candidate threshold
// 2.5 keeps the branch path warp-rare (~55% outer, ~18% per sub-branch) and
// the candidate set small (~153/row). Exact 64th-largest via 8-bit radix
// select over candidates; ties -> lowest index (jax.lax.top_k semantics).
// Rare fallbacks (relu-everywhere / generic key-space radix) keep correctness
// for any input distribution.

constexpr int NCOLS    = 24576;
constexpr int NT       = 512;              // 16 warps
constexpr int NW       = NT / 32;
constexpr int KSEL     = 64;
constexpr int VEC_IT   = NCOLS / (NT * 4); // 12 float4 per thread
constexpr int CAND_MAX = 2048;
constexpr int MAX_EQ   = 128;
constexpr float TCAND  = 2.5f;

constexpr int SMEM_WORDS = 256 + 32 + 4 + 4 + NW + CAND_MAX + CAND_MAX + MAX_EQ;
constexpr int SMEM_BYTES = SMEM_WORDS * 4;

__device__ __forceinline__ uint32_t key_of(uint32_t b) {
    uint32_t mask = (uint32_t)((int32_t)b >> 31) | 0x80000000u;
    return b ^ mask;  // larger float <=> larger unsigned key
}
__device__ __forceinline__ float relu_of_key(uint32_t k) {
    return (k & 0x80000000u) ? __uint_as_float(k ^ 0x80000000u) : 0.0f;
}

// suffix-select over nbins (<=256): thread t holds count v of bin t. Finds bin
// where suffix count crosses rank Kre. Writes sel={bin, strictly_above, count}.
__device__ __forceinline__ void suffix_select(
    uint32_t v, uint32_t* scanb, uint32_t* sel,
    int nbins, uint32_t Kre, int t, int lane, int wid)
{
    uint32_t s = v;  // inclusive suffix within warp
    #pragma unroll
    for (int off = 1; off < 32; off <<= 1) {
        uint32_t u = __shfl_down_sync(0xFFFFFFFFu, s, off);
        if (lane + off < 32) s += u;
    }
    const int nw = (nbins + 31) >> 5;
    if (lane == 0 && wid < nw) scanb[wid] = s;
    __syncthreads();
    if (t < 32) {
        uint32_t w = (t < nw) ? scanb[t] : 0u;
        uint32_t ws = w;
        #pragma unroll
        for (int off = 1; off < 32; off <<= 1) {
            uint32_t u = __shfl_down_sync(0xFFFFFFFFu, ws, off);
            if (t + off < 32) ws += u;
        }
        if (t < nw) scanb[t] = ws - w;   // exclusive suffix over warps above
    }
    __syncthreads();
    if (t < nbins) {
        uint32_t above = (s - v) + scanb[wid];
        if (above < Kre && above + v >= Kre) {
            sel[0] = (uint32_t)t; sel[1] = above; sel[2] = v;
        }
    }
    __syncthreads();
}

__global__ __launch_bounds__(NT, 4)
void topk_relu_kernel(const float* __restrict__ x, float* __restrict__ out) {
    extern __shared__ uint32_t smem[];
    uint32_t* hist  = smem;              // [256]
    uint32_t* scanb = hist + 256;        // [32]
    uint32_t* sel   = scanb + 32;        // [4]
    uint32_t* cnt   = sel + 4;           // [0]=cand, [1]=eq, [2]=npos
    uint32_t* wred  = cnt + 4;           // [NW]
    uint32_t* ck    = wred + NW;         // [CAND_MAX] candidate keys
    uint32_t* ci    = ck + CAND_MAX;     // [CAND_MAX] candidate indices
    uint32_t* eqi   = ci + CAND_MAX;     // [MAX_EQ]

    const int row  = blockIdx.x;
    const int t    = threadIdx.x;
    const int lane = t & 31;
    const int wid  = t >> 5;
    const float4* __restrict__ xv =
        reinterpret_cast<const float4*>(x + (size_t)row * NCOLS);
    float* __restrict__ orow = out + (size_t)row * NCOLS;
    float4* __restrict__ ov = reinterpret_cast<float4*>(orow);

    if (t == 0) { cnt[0] = 0; cnt[1] = 0; }
    __syncthreads();

    // ---- fused main pass: read, zero output, collect candidates ----
    const float4 z4 = make_float4(0.f, 0.f, 0.f, 0.f);
    #pragma unroll 4
    for (int it = 0; it < VEC_IT; it++) {
        int vi = it * NT + t;
        float4 v = __ldcs(xv + vi);
        __stcs(ov + vi, z4);
        float vmax = fmaxf(fmaxf(v.x, v.y), fmaxf(v.z, v.w));
        if (vmax > TCAND) {                 // per-thread rare; warp-taken ~55%
            int base = vi * 4;
            if (v.x > TCAND) { uint32_t p = atomicAdd(&cnt[0], 1u);
                if (p < CAND_MAX) { ck[p] = __float_as_uint(v.x) | 0x80000000u; ci[p] = base; } }
            if (v.y > TCAND) { uint32_t p = atomicAdd(&cnt[0], 1u);
                if (p < CAND_MAX) { ck[p] = __float_as_uint(v.y) | 0x80000000u; ci[p] = base + 1; } }
            if (v.z > TCAND) { uint32_t p = atomicAdd(&cnt[0], 1u);
                if (p < CAND_MAX) { ck[p] = __float_as_uint(v.z) | 0x80000000u; ci[p] = base + 2; } }
            if (v.w > TCAND) { uint32_t p = atomicAdd(&cnt[0], 1u);
                if (p < CAND_MAX) { ck[p] = __float_as_uint(v.w) | 0x80000000u; ci[p] = base + 3; } }
        }
    }
    __syncthreads();

    const uint32_t ncand = cnt[0];

    uint32_t Pc, Rr, nc;
    int shc;
    if (ncand >= KSEL && ncand <= CAND_MAX) {
        // ---- fast path: candidate set complete and contains the top-64 ----
        Pc = 0; shc = 32; Rr = KSEL; nc = ncand;
    } else {
        // ---- rare paths: need the positive count (L2-resident re-read) ----
        uint32_t c0 = 0;
        #pragma unroll 4
        for (int it = 0; it < VEC_IT; it++) {
            float4 v = __ldcs(xv + it * NT + t);
            c0 += (v.x > 0.0f) + (v.y > 0.0f) + (v.z > 0.0f) + (v.w > 0.0f);
        }
        #pragma unroll
        for (int off = 16; off > 0; off >>= 1)
            c0 += __shfl_down_sync(0xFFFFFFFFu, c0, off);
        if (lane == 0) wred[wid] = c0;
        __syncthreads();
        if (t == 0) {
            uint32_t s = 0;
            #pragma unroll
            for (int w = 0; w < NW; w++) s += wred[w];
            cnt[2] = s;
        }
        __syncthreads();
        const uint32_t npos = cnt[2];

        if (npos < KSEL) {
            // 64th largest <= 0: output is exactly relu(x)
            #pragma unroll 4
            for (int it = 0; it < VEC_IT; it++) {
                int vi = it * NT + t;
                float4 v = __ldcs(xv + vi);
                v.x = fmaxf(v.x, 0.0f); v.y = fmaxf(v.y, 0.0f);
                v.z = fmaxf(v.z, 0.0f); v.w = fmaxf(v.w, 0.0f);
                __stcs(ov + vi, v);
            }
            return;
        }

        // generic fallback: key-space radix refine (any distribution)
        const uint32_t* xb = reinterpret_cast<const uint32_t*>(x) + (size_t)row * NCOLS;
        uint32_t P = 0, R = KSEL, bc = NCOLS;
        int sh = 32;
        while (bc > CAND_MAX && sh > 0) {
            int nsh = (sh >= 8) ? sh - 8 : 0;
            int nb  = 1 << (sh - nsh);
            for (int i = t; i < nb; i += NT) hist[i] = 0;
            __syncthreads();
            for (int i = t; i < NCOLS; i += NT) {
                uint32_t k = key_of(xb[i]);
                if (sh == 32 || (k >> sh) == P)
                    atomicAdd(&hist[(k >> nsh) & (nb - 1)], 1u);
            }
            __syncthreads();
            uint32_t hv = (t < nb) ? hist[t] : 0u;
            suffix_select(hv, scanb, sel, nb, R, t, lane, wid);
            P  = ((sh == 32) ? 0u : (P << (sh - nsh))) | sel[0];
            R -= sel[1];
            bc = sel[2];
            sh = nsh;
            __syncthreads();
        }
        const uint32_t kLo = (sh == 32) ? 0u : (P << sh);
        const uint32_t kHi = (sh == 32) ? 0xFFFFFFFFu
                             : (uint32_t)(((((uint64_t)P) + 1ull) << sh) - 1ull);
        if (t == 0) cnt[0] = 0;
        __syncthreads();
        for (int i = t; i < NCOLS; i += NT) {
            uint32_t k = key_of(xb[i]);
            if (k > kHi) {
                orow[i] = relu_of_key(k);       // definitely top-64
            } else if (k >= kLo) {
                uint32_t p = atomicAdd(&cnt[0], 1u);
                if (p < CAND_MAX) { ck[p] = k; ci[p] = (uint32_t)i; }
            }
        }
        __syncthreads();
        nc = cnt[0]; if (nc > CAND_MAX) nc = CAND_MAX;
        Pc = P; shc = sh; Rr = R;
    }

    // ---- exact threshold: 8-bit radix select over candidates ----
    while (shc > 0) {
        int nsh = (shc >= 8) ? shc - 8 : 0;
        int nb  = 1 << (shc - nsh);
        for (int i = t; i < nb; i += NT) hist[i] = 0;
        __syncthreads();
        for (uint32_t i = t; i < nc; i += NT) {
            uint32_t k = ck[i];
            if (shc == 32 || (k >> shc) == Pc)
                atomicAdd(&hist[(k >> nsh) & (nb - 1)], 1u);
        }
        __syncthreads();
        uint32_t hv = (t < nb) ? hist[t] : 0u;
        suffix_select(hv, scanb, sel, nb, Rr, t, lane, wid);
        Pc  = ((shc == 32) ? 0u : (Pc << (shc - nsh))) | sel[0];
        Rr -= sel[1];
        shc = nsh;
        __syncthreads();
    }
    const uint32_t Tkey   = Pc;
    const uint32_t keepEq = Rr;                 // # threshold-equal keys to keep
    const float    tval   = relu_of_key(Tkey);

    // ---- scatter strictly-above candidates; collect exact ties ----
    for (uint32_t i = t; i < nc; i += NT) {
        uint32_t k = ck[i];
        if (k > Tkey) {
            orow[ci[i]] = relu_of_key(k);
        } else if (k == Tkey) {
            uint32_t p = atomicAdd(&cnt[1], 1u);
            if (p < MAX_EQ) eqi[p] = ci[i];
        }
    }
    __syncthreads();

    // ---- ties: keep the keepEq equal-keys with smallest indices ----
    uint32_t ne = cnt[1];
    if (ne > MAX_EQ) ne = MAX_EQ;
    if (ne <= keepEq) {
        for (uint32_t e = t; e < ne; e += NT) orow[eqi[e]] = tval;
    } else {
        for (uint32_t e = t; e < ne; e += NT) {
            uint32_t idx = eqi[e];
            uint32_t c = 0;
            for (uint32_t j = 0; j < ne; j++) c += (eqi[j] < idx);
            if (c < keepEq) orow[idx] = tval;
        }
    }
}

extern "C" void kernel_launch(void* const* d_in, const int* in_sizes, int n_in,
                              void* d_out, int out_size) {
    const float* x = (const float*)d_in[0];
    float* out = (float*)d_out;
    const int rows = in_sizes[0] / NCOLS;

    cudaFuncSetAttribute(topk_relu_kernel,
                         cudaFuncAttributeMaxDynamicSharedMemorySize, SMEM_BYTES);
    topk_relu_kernel<<<rows, NT, SMEM_BYTES>>>(x, out);
}

// round 11
// speedup vs baseline: 1.2774x; 1.0363x over previous
#include <cuda_runtime.h>
#include <cstdint>

// Top-64 per row with ReLU, zeros elsewhere. One CTA per row, SINGLE fused
// data pass (read + zero-store + candidate collection, TCAND=2.5 ->
// ~150 candidates/row). Fast-path selection: all-pairs rank over candidates
// (one thread per candidate, broadcast SMEM scans) — exact top-64 with
// jax.lax.top_k tie semantics (lowest index wins) in ~2 barriers.
// Radix select kept for nc>512; generic fallbacks (relu-everywhere /
// key-space radix refine) keep correctness for any input distribution.

constexpr int NCOLS    = 24576;
constexpr int NT       = 512;              // 16 warps
constexpr int NW       = NT / 32;
constexpr int KSEL     = 64;
constexpr int VEC_IT   = NCOLS / (NT * 4); // 12 float4 per thread
constexpr int CAND_MAX = 2048;
constexpr int MAX_EQ   = 128;
constexpr float TCAND  = 2.5f;

constexpr int SMEM_WORDS = 256 + 32 + 4 + 4 + NW + CAND_MAX + CAND_MAX + MAX_EQ;
constexpr int SMEM_BYTES = SMEM_WORDS * 4;

__device__ __forceinline__ uint32_t key_of(uint32_t b) {
    uint32_t mask = (uint32_t)((int32_t)b >> 31) | 0x80000000u;
    return b ^ mask;  // larger float <=> larger unsigned key
}
__device__ __forceinline__ float relu_of_key(uint32_t k) {
    return (k & 0x80000000u) ? __uint_as_float(k ^ 0x80000000u) : 0.0f;
}

// suffix-select over nbins (<=256): thread t holds count v of bin t. Finds bin
// where suffix count crosses rank Kre. Writes sel={bin, strictly_above, count}.
__device__ __forceinline__ void suffix_select(
    uint32_t v, uint32_t* scanb, uint32_t* sel,
    int nbins, uint32_t Kre, int t, int lane, int wid)
{
    uint32_t s = v;  // inclusive suffix within warp
    #pragma unroll
    for (int off = 1; off < 32; off <<= 1) {
        uint32_t u = __shfl_down_sync(0xFFFFFFFFu, s, off);
        if (lane + off < 32) s += u;
    }
    const int nw = (nbins + 31) >> 5;
    if (lane == 0 && wid < nw) scanb[wid] = s;
    __syncthreads();
    if (t < 32) {
        uint32_t w = (t < nw) ? scanb[t] : 0u;
        uint32_t ws = w;
        #pragma unroll
        for (int off = 1; off < 32; off <<= 1) {
            uint32_t u = __shfl_down_sync(0xFFFFFFFFu, ws, off);
            if (t + off < 32) ws += u;
        }
        if (t < nw) scanb[t] = ws - w;   // exclusive suffix over warps above
    }
    __syncthreads();
    if (t < nbins) {
        uint32_t above = (s - v) + scanb[wid];
        if (above < Kre && above + v >= Kre) {
            sel[0] = (uint32_t)t; sel[1] = above; sel[2] = v;
        }
    }
    __syncthreads();
}

__global__ __launch_bounds__(NT, 4)
void topk_relu_kernel(const float* __restrict__ x, float* __restrict__ out) {
    extern __shared__ uint32_t smem[];
    uint32_t* hist  = smem;              // [256]
    uint32_t* scanb = hist + 256;        // [32]
    uint32_t* sel   = scanb + 32;        // [4]
    uint32_t* cnt   = sel + 4;           // [0]=cand, [1]=eq, [2]=npos
    uint32_t* wred  = cnt + 4;           // [NW]
    uint32_t* ck    = wred + NW;         // [CAND_MAX] candidate keys
    uint32_t* ci    = ck + CAND_MAX;     // [CAND_MAX] candidate indices
    uint32_t* eqi   = ci + CAND_MAX;     // [MAX_EQ]

    const int row  = blockIdx.x;
    const int t    = threadIdx.x;
    const int lane = t & 31;
    const int wid  = t >> 5;
    const float4* __restrict__ xv =
        reinterpret_cast<const float4*>(x + (size_t)row * NCOLS);
    float* __restrict__ orow = out + (size_t)row * NCOLS;
    float4* __restrict__ ov = reinterpret_cast<float4*>(orow);

    if (t == 0) { cnt[0] = 0; cnt[1] = 0; }
    __syncthreads();

    // ---- fused main pass: read, zero output, collect candidates ----
    const float4 z4 = make_float4(0.f, 0.f, 0.f, 0.f);
    #pragma unroll 4
    for (int it = 0; it < VEC_IT; it++) {
        int vi = it * NT + t;
        float4 v = __ldcs(xv + vi);
        __stcs(ov + vi, z4);
        float vmax = fmaxf(fmaxf(v.x, v.y), fmaxf(v.z, v.w));
        if (vmax > TCAND) {                 // per-thread rare
            int base = vi * 4;
            if (v.x > TCAND) { uint32_t p = atomicAdd(&cnt[0], 1u);
                if (p < CAND_MAX) { ck[p] = __float_as_uint(v.x) | 0x80000000u; ci[p] = base; } }
            if (v.y > TCAND) { uint32_t p = atomicAdd(&cnt[0], 1u);
                if (p < CAND_MAX) { ck[p] = __float_as_uint(v.y) | 0x80000000u; ci[p] = base + 1; } }
            if (v.z > TCAND) { uint32_t p = atomicAdd(&cnt[0], 1u);
                if (p < CAND_MAX) { ck[p] = __float_as_uint(v.z) | 0x80000000u; ci[p] = base + 2; } }
            if (v.w > TCAND) { uint32_t p = atomicAdd(&cnt[0], 1u);
                if (p < CAND_MAX) { ck[p] = __float_as_uint(v.w) | 0x80000000u; ci[p] = base + 3; } }
        }
    }
    __syncthreads();

    const uint32_t ncand = cnt[0];

    // ---- fast path A: rank epilogue (one thread per candidate) ----
    if (ncand >= KSEL && ncand <= (uint32_t)NT) {
        uint32_t myk = 0, myi = 0;
        if (t < (int)ncand) { myk = ck[t]; myi = ci[t]; }
        uint32_t r = 0;
        if (t < (int)ncand) {
            for (uint32_t j = 0; j < ncand; j++) {
                uint32_t kj = ck[j];
                uint32_t ij = ci[j];
                r += (kj > myk) || (kj == myk && ij < myi);
            }
            if (r < KSEL) orow[myi] = relu_of_key(myk);
        }
        return;
    }

    uint32_t Pc, Rr, nc;
    int shc;
    if (ncand > (uint32_t)NT && ncand <= CAND_MAX) {
        // ---- fast path B: larger candidate set -> radix select ----
        Pc = 0; shc = 32; Rr = KSEL; nc = ncand;
    } else {
        // ---- rare paths: need the positive count (L2-resident re-read) ----
        uint32_t c0 = 0;
        #pragma unroll 4
        for (int it = 0; it < VEC_IT; it++) {
            float4 v = __ldcs(xv + it * NT + t);
            c0 += (v.x > 0.0f) + (v.y > 0.0f) + (v.z > 0.0f) + (v.w > 0.0f);
        }
        #pragma unroll
        for (int off = 16; off > 0; off >>= 1)
            c0 += __shfl_down_sync(0xFFFFFFFFu, c0, off);
        if (lane == 0) wred[wid] = c0;
        __syncthreads();
        if (t == 0) {
            uint32_t s = 0;
            #pragma unroll
            for (int w = 0; w < NW; w++) s += wred[w];
            cnt[2] = s;
        }
        __syncthreads();
        const uint32_t npos = cnt[2];

        if (npos < KSEL) {
            // 64th largest <= 0: output is exactly relu(x)
            #pragma unroll 4
            for (int it = 0; it < VEC_IT; it++) {
                int vi = it * NT + t;
                float4 v = __ldcs(xv + vi);
                v.x = fmaxf(v.x, 0.0f); v.y = fmaxf(v.y, 0.0f);
                v.z = fmaxf(v.z, 0.0f); v.w = fmaxf(v.w, 0.0f);
                __stcs(ov + vi, v);
            }
            return;
        }

        // generic fallback: key-space radix refine (any distribution)
        const uint32_t* xb = reinterpret_cast<const uint32_t*>(x) + (size_t)row * NCOLS;
        uint32_t P = 0, R = KSEL, bc = NCOLS;
        int sh = 32;
        while (bc > CAND_MAX && sh > 0) {
            int nsh = (sh >= 8) ? sh - 8 : 0;
            int nb  = 1 << (sh - nsh);
            for (int i = t; i < nb; i += NT) hist[i] = 0;
            __syncthreads();
            for (int i = t; i < NCOLS; i += NT) {
                uint32_t k = key_of(xb[i]);
                if (sh == 32 || (k >> sh) == P)
                    atomicAdd(&hist[(k >> nsh) & (nb - 1)], 1u);
            }
            __syncthreads();
            uint32_t hv = (t < nb) ? hist[t] : 0u;
            suffix_select(hv, scanb, sel, nb, R, t, lane, wid);
            P  = ((sh == 32) ? 0u : (P << (sh - nsh))) | sel[0];
            R -= sel[1];
            bc = sel[2];
            sh = nsh;
            __syncthreads();
        }
        const uint32_t kLo = (sh == 32) ? 0u : (P << sh);
        const uint32_t kHi = (sh == 32) ? 0xFFFFFFFFu
                             : (uint32_t)(((((uint64_t)P) + 1ull) << sh) - 1ull);
        if (t == 0) cnt[0] = 0;
        __syncthreads();
        for (int i = t; i < NCOLS; i += NT) {
            uint32_t k = key_of(xb[i]);
            if (k > kHi) {
                orow[i] = relu_of_key(k);       // definitely top-64
            } else if (k >= kLo) {
                uint32_t p = atomicAdd(&cnt[0], 1u);
                if (p < CAND_MAX) { ck[p] = k; ci[p] = (uint32_t)i; }
            }
        }
        __syncthreads();
        nc = cnt[0]; if (nc > CAND_MAX) nc = CAND_MAX;
        Pc = P; shc = sh; Rr = R;
    }

    // ---- exact threshold: 8-bit radix select over candidates ----
    while (shc > 0) {
        int nsh = (shc >= 8) ? shc - 8 : 0;
        int nb  = 1 << (shc - nsh);
        for (int i = t; i < nb; i += NT) hist[i] = 0;
        __syncthreads();
        for (uint32_t i = t; i < nc; i += NT) {
            uint32_t k = ck[i];
            if (shc == 32 || (k >> shc) == Pc)
                atomicAdd(&hist[(k >> nsh) & (nb - 1)], 1u);
        }
        __syncthreads();
        uint32_t hv = (t < nb) ? hist[t] : 0u;
        suffix_select(hv, scanb, sel, nb, Rr, t, lane, wid);
        Pc  = ((shc == 32) ? 0u : (Pc << (shc - nsh))) | sel[0];
        Rr -= sel[1];
        shc = nsh;
        __syncthreads();
    }
    const uint32_t Tkey   = Pc;
    const uint32_t keepEq = Rr;                 // # threshold-equal keys to keep
    const float    tval   = relu_of_key(Tkey);

    // ---- scatter strictly-above candidates; collect exact ties ----
    for (uint32_t i = t; i < nc; i += NT) {
        uint32_t k = ck[i];
        if (k > Tkey) {
            orow[ci[i]] = relu_of_key(k);
        } else if (k == Tkey) {
            uint32_t p = atomicAdd(&cnt[1], 1u);
            if (p < MAX_EQ) eqi[p] = ci[i];
        }
    }
    __syncthreads();

    // ---- ties: keep the keepEq equal-keys with smallest indices ----
    uint32_t ne = cnt[1];
    if (ne > MAX_EQ) ne = MAX_EQ;
    if (ne <= keepEq) {
        for (uint32_t e = t; e < ne; e += NT) orow[eqi[e]] = tval;
    } else {
        for (uint32_t e = t; e < ne; e += NT) {
            uint32_t idx = eqi[e];
            uint32_t c = 0;
            for (uint32_t j = 0; j < ne; j++) c += (eqi[j] < idx);
            if (c < keepEq) orow[idx] = tval;
        }
    }
}

extern "C" void kernel_launch(void* const* d_in, const int* in_sizes, int n_in,
                              void* d_out, int out_size) {
    const float* x = (const float*)d_in[0];
    float* out = (float*)d_out;
    const int rows = in_sizes[0] / NCOLS;

    cudaFuncSetAttribute(topk_relu_kernel,
                         cudaFuncAttributeMaxDynamicSharedMemorySize, SMEM_BYTES);
    topk_relu_kernel<<<rows, NT, SMEM_BYTES>>>(x, out);
}

// round 12
// speedup vs baseline: 1.4567x; 1.1403x over previous
#include <cuda_runtime.h>
#include <cstdint>

// Top-64 per row with ReLU, zeros elsewhere. One CTA per row, SINGLE fused
// data pass (paired-load software pipeline: 2x LDG batched before 2x STG).
// TCAND=2.6 -> ~114 candidates/row. Fast-path selection: all-pairs rank over
// candidates (one thread per candidate, broadcast SMEM scans) with
// jax.lax.top_k tie semantics (lowest index wins). Radix select for nc>512;
// generic fallbacks (relu-everywhere / key-space radix refine) keep
// correctness for any input distribution.

constexpr int NCOLS    = 24576;
constexpr int NT       = 512;              // 16 warps
constexpr int NW       = NT / 32;
constexpr int KSEL     = 64;
constexpr int VEC_IT   = NCOLS / (NT * 4); // 12 float4 per thread
constexpr int CAND_MAX = 2048;
constexpr int MAX_EQ   = 128;
constexpr float TCAND  = 2.6f;

constexpr int SMEM_WORDS = 256 + 32 + 4 + 4 + NW + CAND_MAX + CAND_MAX + MAX_EQ;
constexpr int SMEM_BYTES = SMEM_WORDS * 4;

__device__ __forceinline__ uint32_t key_of(uint32_t b) {
    uint32_t mask = (uint32_t)((int32_t)b >> 31) | 0x80000000u;
    return b ^ mask;  // larger float <=> larger unsigned key
}
__device__ __forceinline__ float relu_of_key(uint32_t k) {
    return (k & 0x80000000u) ? __uint_as_float(k ^ 0x80000000u) : 0.0f;
}

__device__ __forceinline__ void collect4(
    const float4& v, int base, uint32_t* cnt, uint32_t* ck, uint32_t* ci)
{
    if (v.x > TCAND) { uint32_t p = atomicAdd(&cnt[0], 1u);
        if (p < CAND_MAX) { ck[p] = __float_as_uint(v.x) | 0x80000000u; ci[p] = base; } }
    if (v.y > TCAND) { uint32_t p = atomicAdd(&cnt[0], 1u);
        if (p < CAND_MAX) { ck[p] = __float_as_uint(v.y) | 0x80000000u; ci[p] = base + 1; } }
    if (v.z > TCAND) { uint32_t p = atomicAdd(&cnt[0], 1u);
        if (p < CAND_MAX) { ck[p] = __float_as_uint(v.z) | 0x80000000u; ci[p] = base + 2; } }
    if (v.w > TCAND) { uint32_t p = atomicAdd(&cnt[0], 1u);
        if (p < CAND_MAX) { ck[p] = __float_as_uint(v.w) | 0x80000000u; ci[p] = base + 3; } }
}

// suffix-select over nbins (<=256): thread t holds count v of bin t. Finds bin
// where suffix count crosses rank Kre. Writes sel={bin, strictly_above, count}.
__device__ __forceinline__ void suffix_select(
    uint32_t v, uint32_t* scanb, uint32_t* sel,
    int nbins, uint32_t Kre, int t, int lane, int wid)
{
    uint32_t s = v;  // inclusive suffix within warp
    #pragma unroll
    for (int off = 1; off < 32; off <<= 1) {
        uint32_t u = __shfl_down_sync(0xFFFFFFFFu, s, off);
        if (lane + off < 32) s += u;
    }
    const int nw = (nbins + 31) >> 5;
    if (lane == 0 && wid < nw) scanb[wid] = s;
    __syncthreads();
    if (t < 32) {
        uint32_t w = (t < nw) ? scanb[t] : 0u;
        uint32_t ws = w;
        #pragma unroll
        for (int off = 1; off < 32; off <<= 1) {
            uint32_t u = __shfl_down_sync(0xFFFFFFFFu, ws, off);
            if (t + off < 32) ws += u;
        }
        if (t < nw) scanb[t] = ws - w;   // exclusive suffix over warps above
    }
    __syncthreads();
    if (t < nbins) {
        uint32_t above = (s - v) + scanb[wid];
        if (above < Kre && above + v >= Kre) {
            sel[0] = (uint32_t)t; sel[1] = above; sel[2] = v;
        }
    }
    __syncthreads();
}

__global__ __launch_bounds__(NT, 4)
void topk_relu_kernel(const float* __restrict__ x, float* __restrict__ out) {
    extern __shared__ uint32_t smem[];
    uint32_t* hist  = smem;              // [256]
    uint32_t* scanb = hist + 256;        // [32]
    uint32_t* sel   = scanb + 32;        // [4]
    uint32_t* cnt   = sel + 4;           // [0]=cand, [1]=eq, [2]=npos
    uint32_t* wred  = cnt + 4;           // [NW]
    uint32_t* ck    = wred + NW;         // [CAND_MAX] candidate keys
    uint32_t* ci    = ck + CAND_MAX;     // [CAND_MAX] candidate indices
    uint32_t* eqi   = ci + CAND_MAX;     // [MAX_EQ]

    const int row  = blockIdx.x;
    const int t    = threadIdx.x;
    const int lane = t & 31;
    const int wid  = t >> 5;
    const float4* __restrict__ xv =
        reinterpret_cast<const float4*>(x + (size_t)row * NCOLS);
    float* __restrict__ orow = out + (size_t)row * NCOLS;
    float4* __restrict__ ov = reinterpret_cast<float4*>(orow);

    if (t == 0) { cnt[0] = 0; cnt[1] = 0; }
    __syncthreads();

    // ---- fused main pass: paired loads, paired zero-stores, collect cands ----
    const float4 z4 = make_float4(0.f, 0.f, 0.f, 0.f);
    #pragma unroll
    for (int it = 0; it < VEC_IT; it += 2) {
        int vi0 = it * NT + t;
        int vi1 = (it + 1) * NT + t;
        float4 v0 = __ldcs(xv + vi0);
        float4 v1 = __ldcs(xv + vi1);
        __stcs(ov + vi0, z4);
        __stcs(ov + vi1, z4);
        float m0 = fmaxf(fmaxf(v0.x, v0.y), fmaxf(v0.z, v0.w));
        float m1 = fmaxf(fmaxf(v1.x, v1.y), fmaxf(v1.z, v1.w));
        if (m0 > TCAND) collect4(v0, vi0 * 4, cnt, ck, ci);
        if (m1 > TCAND) collect4(v1, vi1 * 4, cnt, ck, ci);
    }
    __syncthreads();

    const uint32_t ncand = cnt[0];

    // ---- fast path A: rank epilogue (one thread per candidate) ----
    if (ncand >= KSEL && ncand <= (uint32_t)NT) {
        if (t < (int)ncand) {
            uint32_t myk = ck[t], myi = ci[t];
            uint32_t r = 0;
            for (uint32_t j = 0; j < ncand; j++) {
                uint32_t kj = ck[j];
                uint32_t ij = ci[j];
                r += (kj > myk) || (kj == myk && ij < myi);
            }
            if (r < KSEL) orow[myi] = relu_of_key(myk);
        }
        return;
    }

    uint32_t Pc, Rr, nc;
    int shc;
    if (ncand > (uint32_t)NT && ncand <= CAND_MAX) {
        // ---- fast path B: larger candidate set -> radix select ----
        Pc = 0; shc = 32; Rr = KSEL; nc = ncand;
    } else {
        // ---- rare paths: need the positive count (L2-resident re-read) ----
        uint32_t c0 = 0;
        #pragma unroll 4
        for (int it = 0; it < VEC_IT; it++) {
            float4 v = __ldcs(xv + it * NT + t);
            c0 += (v.x > 0.0f) + (v.y > 0.0f) + (v.z > 0.0f) + (v.w > 0.0f);
        }
        #pragma unroll
        for (int off = 16; off > 0; off >>= 1)
            c0 += __shfl_down_sync(0xFFFFFFFFu, c0, off);
        if (lane == 0) wred[wid] = c0;
        __syncthreads();
        if (t == 0) {
            uint32_t s = 0;
            #pragma unroll
            for (int w = 0; w < NW; w++) s += wred[w];
            cnt[2] = s;
        }
        __syncthreads();
        const uint32_t npos = cnt[2];

        if (npos < KSEL) {
            // 64th largest <= 0: output is exactly relu(x)
            #pragma unroll 4
            for (int it = 0; it < VEC_IT; it++) {
                int vi = it * NT + t;
                float4 v = __ldcs(xv + vi);
                v.x = fmaxf(v.x, 0.0f); v.y = fmaxf(v.y, 0.0f);
                v.z = fmaxf(v.z, 0.0f); v.w = fmaxf(v.w, 0.0f);
                __stcs(ov + vi, v);
            }
            return;
        }

        // generic fallback: key-space radix refine (any distribution)
        const uint32_t* xb = reinterpret_cast<const uint32_t*>(x) + (size_t)row * NCOLS;
        uint32_t P = 0, R = KSEL, bc = NCOLS;
        int sh = 32;
        while (bc > CAND_MAX && sh > 0) {
            int nsh = (sh >= 8) ? sh - 8 : 0;
            int nb  = 1 << (sh - nsh);
            for (int i = t; i < nb; i += NT) hist[i] = 0;
            __syncthreads();
            for (int i = t; i < NCOLS; i += NT) {
                uint32_t k = key_of(xb[i]);
                if (sh == 32 || (k >> sh) == P)
                    atomicAdd(&hist[(k >> nsh) & (nb - 1)], 1u);
            }
            __syncthreads();
            uint32_t hv = (t < nb) ? hist[t] : 0u;
            suffix_select(hv, scanb, sel, nb, R, t, lane, wid);
            P  = ((sh == 32) ? 0u : (P << (sh - nsh))) | sel[0];
            R -= sel[1];
            bc = sel[2];
            sh = nsh;
            __syncthreads();
        }
        const uint32_t kLo = (sh == 32) ? 0u : (P << sh);
        const uint32_t kHi = (sh == 32) ? 0xFFFFFFFFu
                             : (uint32_t)(((((uint64_t)P) + 1ull) << sh) - 1ull);
        if (t == 0) cnt[0] = 0;
        __syncthreads();
        for (int i = t; i < NCOLS; i += NT) {
            uint32_t k = key_of(xb[i]);
            if (k > kHi) {
                orow[i] = relu_of_key(k);       // definitely top-64
            } else if (k >= kLo) {
                uint32_t p = atomicAdd(&cnt[0], 1u);
                if (p < CAND_MAX) { ck[p] = k; ci[p] = (uint32_t)i; }
            }
        }
        __syncthreads();
        nc = cnt[0]; if (nc > CAND_MAX) nc = CAND_MAX;
        Pc = P; shc = sh; Rr = R;
    }

    // ---- exact threshold: 8-bit radix select over candidates ----
    while (shc > 0) {
        int nsh = (shc >= 8) ? shc - 8 : 0;
        int nb  = 1 << (shc - nsh);
        for (int i = t; i < nb; i += NT) hist[i] = 0;
        __syncthreads();
        for (uint32_t i = t; i < nc; i += NT) {
            uint32_t k = ck[i];
            if (shc == 32 || (k >> shc) == Pc)
                atomicAdd(&hist[(k >> nsh) & (nb - 1)], 1u);
        }
        __syncthreads();
        uint32_t hv = (t < nb) ? hist[t] : 0u;
        suffix_select(hv, scanb, sel, nb, Rr, t, lane, wid);
        Pc  = ((shc == 32) ? 0u : (Pc << (shc - nsh))) | sel[0];
        Rr -= sel[1];
        shc = nsh;
        __syncthreads();
    }
    const uint32_t Tkey   = Pc;
    const uint32_t keepEq = Rr;                 // # threshold-equal keys to keep
    const float    tval   = relu_of_key(Tkey);

    // ---- scatter strictly-above candidates; collect exact ties ----
    for (uint32_t i = t; i < nc; i += NT) {
        uint32_t k = ck[i];
        if (k > Tkey) {
            orow[ci[i]] = relu_of_key(k);
        } else if (k == Tkey) {
            uint32_t p = atomicAdd(&cnt[1], 1u);
            if (p < MAX_EQ) eqi[p] = ci[i];
        }
    }
    __syncthreads();

    // ---- ties: keep the keepEq equal-keys with smallest indices ----
    uint32_t ne = cnt[1];
    if (ne > MAX_EQ) ne = MAX_EQ;
    if (ne <= keepEq) {
        for (uint32_t e = t; e < ne; e += NT) orow[eqi[e]] = tval;
    } else {
        for (uint32_t e = t; e < ne; e += NT) {
            uint32_t idx = eqi[e];
            uint32_t c = 0;
            for (uint32_t j = 0; j < ne; j++) c += (eqi[j] < idx);
            if (c < keepEq) orow[idx] = tval;
        }
    }
}

extern "C" void kernel_launch(void* const* d_in, const int* in_sizes, int n_in,
                              void* d_out, int out_size) {
    const float* x = (const float*)d_in[0];
    float* out = (float*)d_out;
    const int rows = in_sizes[0] / NCOLS;

    cudaFuncSetAttribute(topk_relu_kernel,
                         cudaFuncAttributeMaxDynamicSharedMemorySize, SMEM_BYTES);
    topk_relu_kernel<<<rows, NT, SMEM_BYTES>>>(x, out);
}

// round 13
// speedup vs baseline: 1.4864x; 1.0205x over previous
#include <cuda_runtime.h>
#include <cstdint>

// Top-64 per row with ReLU, zeros elsewhere. One CTA per row, SINGLE fused
// data pass with 4-deep load batching (4x LDG.128 front-batched before
// 4x STG.128 zero-stores) for deep memory-level parallelism.
// TCAND=2.6 -> ~114 candidates/row. Fast-path selection: all-pairs rank over
// candidates (one thread per candidate, broadcast SMEM scans) with
// jax.lax.top_k tie semantics (lowest index wins). Radix select for nc>512;
// generic fallbacks (relu-everywhere / key-space radix refine) keep
// correctness for any input distribution.

constexpr int NCOLS    = 24576;
constexpr int NT       = 512;              // 16 warps
constexpr int NW       = NT / 32;
constexpr int KSEL     = 64;
constexpr int VEC_IT   = NCOLS / (NT * 4); // 12 float4 per thread
constexpr int CAND_MAX = 2048;
constexpr int MAX_EQ   = 128;
constexpr float TCAND  = 2.6f;

constexpr int SMEM_WORDS = 256 + 32 + 4 + 4 + NW + CAND_MAX + CAND_MAX + MAX_EQ;
constexpr int SMEM_BYTES = SMEM_WORDS * 4;

__device__ __forceinline__ uint32_t key_of(uint32_t b) {
    uint32_t mask = (uint32_t)((int32_t)b >> 31) | 0x80000000u;
    return b ^ mask;  // larger float <=> larger unsigned key
}
__device__ __forceinline__ float relu_of_key(uint32_t k) {
    return (k & 0x80000000u) ? __uint_as_float(k ^ 0x80000000u) : 0.0f;
}

__device__ __forceinline__ void collect4(
    const float4& v, int base, uint32_t* cnt, uint32_t* ck, uint32_t* ci)
{
    if (v.x > TCAND) { uint32_t p = atomicAdd(&cnt[0], 1u);
        if (p < CAND_MAX) { ck[p] = __float_as_uint(v.x) | 0x80000000u; ci[p] = base; } }
    if (v.y > TCAND) { uint32_t p = atomicAdd(&cnt[0], 1u);
        if (p < CAND_MAX) { ck[p] = __float_as_uint(v.y) | 0x80000000u; ci[p] = base + 1; } }
    if (v.z > TCAND) { uint32_t p = atomicAdd(&cnt[0], 1u);
        if (p < CAND_MAX) { ck[p] = __float_as_uint(v.z) | 0x80000000u; ci[p] = base + 2; } }
    if (v.w > TCAND) { uint32_t p = atomicAdd(&cnt[0], 1u);
        if (p < CAND_MAX) { ck[p] = __float_as_uint(v.w) | 0x80000000u; ci[p] = base + 3; } }
}

// suffix-select over nbins (<=256): thread t holds count v of bin t. Finds bin
// where suffix count crosses rank Kre. Writes sel={bin, strictly_above, count}.
__device__ __forceinline__ void suffix_select(
    uint32_t v, uint32_t* scanb, uint32_t* sel,
    int nbins, uint32_t Kre, int t, int lane, int wid)
{
    uint32_t s = v;  // inclusive suffix within warp
    #pragma unroll
    for (int off = 1; off < 32; off <<= 1) {
        uint32_t u = __shfl_down_sync(0xFFFFFFFFu, s, off);
        if (lane + off < 32) s += u;
    }
    const int nw = (nbins + 31) >> 5;
    if (lane == 0 && wid < nw) scanb[wid] = s;
    __syncthreads();
    if (t < 32) {
        uint32_t w = (t < nw) ? scanb[t] : 0u;
        uint32_t ws = w;
        #pragma unroll
        for (int off = 1; off < 32; off <<= 1) {
            uint32_t u = __shfl_down_sync(0xFFFFFFFFu, ws, off);
            if (t + off < 32) ws += u;
        }
        if (t < nw) scanb[t] = ws - w;   // exclusive suffix over warps above
    }
    __syncthreads();
    if (t < nbins) {
        uint32_t above = (s - v) + scanb[wid];
        if (above < Kre && above + v >= Kre) {
            sel[0] = (uint32_t)t; sel[1] = above; sel[2] = v;
        }
    }
    __syncthreads();
}

__global__ __launch_bounds__(NT, 4)
void topk_relu_kernel(const float* __restrict__ x, float* __restrict__ out) {
    extern __shared__ uint32_t smem[];
    uint32_t* hist  = smem;              // [256]
    uint32_t* scanb = hist + 256;        // [32]
    uint32_t* sel   = scanb + 32;        // [4]
    uint32_t* cnt   = sel + 4;           // [0]=cand, [1]=eq, [2]=npos
    uint32_t* wred  = cnt + 4;           // [NW]
    uint32_t* ck    = wred + NW;         // [CAND_MAX] candidate keys
    uint32_t* ci    = ck + CAND_MAX;     // [CAND_MAX] candidate indices
    uint32_t* eqi   = ci + CAND_MAX;     // [MAX_EQ]

    const int row  = blockIdx.x;
    const int t    = threadIdx.x;
    const int lane = t & 31;
    const int wid  = t >> 5;
    const float4* __restrict__ xv =
        reinterpret_cast<const float4*>(x + (size_t)row * NCOLS);
    float* __restrict__ orow = out + (size_t)row * NCOLS;
    float4* __restrict__ ov = reinterpret_cast<float4*>(orow);

    if (t == 0) { cnt[0] = 0; cnt[1] = 0; }
    __syncthreads();

    // ---- fused main pass: 4 front-batched loads, 4 zero-stores, collect ----
    const float4 z4 = make_float4(0.f, 0.f, 0.f, 0.f);
    #pragma unroll
    for (int it = 0; it < VEC_IT; it += 4) {
        int vi0 = (it + 0) * NT + t;
        int vi1 = (it + 1) * NT + t;
        int vi2 = (it + 2) * NT + t;
        int vi3 = (it + 3) * NT + t;
        float4 v0 = __ldcs(xv + vi0);
        float4 v1 = __ldcs(xv + vi1);
        float4 v2 = __ldcs(xv + vi2);
        float4 v3 = __ldcs(xv + vi3);
        __stcs(ov + vi0, z4);
        __stcs(ov + vi1, z4);
        __stcs(ov + vi2, z4);
        __stcs(ov + vi3, z4);
        float m0 = fmaxf(fmaxf(v0.x, v0.y), fmaxf(v0.z, v0.w));
        float m1 = fmaxf(fmaxf(v1.x, v1.y), fmaxf(v1.z, v1.w));
        float m2 = fmaxf(fmaxf(v2.x, v2.y), fmaxf(v2.z, v2.w));
        float m3 = fmaxf(fmaxf(v3.x, v3.y), fmaxf(v3.z, v3.w));
        if (m0 > TCAND) collect4(v0, vi0 * 4, cnt, ck, ci);
        if (m1 > TCAND) collect4(v1, vi1 * 4, cnt, ck, ci);
        if (m2 > TCAND) collect4(v2, vi2 * 4, cnt, ck, ci);
        if (m3 > TCAND) collect4(v3, vi3 * 4, cnt, ck, ci);
    }
    __syncthreads();

    const uint32_t ncand = cnt[0];

    // ---- fast path A: rank epilogue (one thread per candidate) ----
    if (ncand >= KSEL && ncand <= (uint32_t)NT) {
        if (t < (int)ncand) {
            uint32_t myk = ck[t], myi = ci[t];
            uint32_t r = 0;
            for (uint32_t j = 0; j < ncand; j++) {
                uint32_t kj = ck[j];
                uint32_t ij = ci[j];
                r += (kj > myk) || (kj == myk && ij < myi);
            }
            if (r < KSEL) orow[myi] = relu_of_key(myk);
        }
        return;
    }

    uint32_t Pc, Rr, nc;
    int shc;
    if (ncand > (uint32_t)NT && ncand <= CAND_MAX) {
        // ---- fast path B: larger candidate set -> radix select ----
        Pc = 0; shc = 32; Rr = KSEL; nc = ncand;
    } else {
        // ---- rare paths: need the positive count (L2-resident re-read) ----
        uint32_t c0 = 0;
        #pragma unroll 4
        for (int it = 0; it < VEC_IT; it++) {
            float4 v = __ldcs(xv + it * NT + t);
            c0 += (v.x > 0.0f) + (v.y > 0.0f) + (v.z > 0.0f) + (v.w > 0.0f);
        }
        #pragma unroll
        for (int off = 16; off > 0; off >>= 1)
            c0 += __shfl_down_sync(0xFFFFFFFFu, c0, off);
        if (lane == 0) wred[wid] = c0;
        __syncthreads();
        if (t == 0) {
            uint32_t s = 0;
            #pragma unroll
            for (int w = 0; w < NW; w++) s += wred[w];
            cnt[2] = s;
        }
        __syncthreads();
        const uint32_t npos = cnt[2];

        if (npos < KSEL) {
            // 64th largest <= 0: output is exactly relu(x)
            #pragma unroll 4
            for (int it = 0; it < VEC_IT; it++) {
                int vi = it * NT + t;
                float4 v = __ldcs(xv + vi);
                v.x = fmaxf(v.x, 0.0f); v.y = fmaxf(v.y, 0.0f);
                v.z = fmaxf(v.z, 0.0f); v.w = fmaxf(v.w, 0.0f);
                __stcs(ov + vi, v);
            }
            return;
        }

        // generic fallback: key-space radix refine (any distribution)
        const uint32_t* xb = reinterpret_cast<const uint32_t*>(x) + (size_t)row * NCOLS;
        uint32_t P = 0, R = KSEL, bc = NCOLS;
        int sh = 32;
        while (bc > CAND_MAX && sh > 0) {
            int nsh = (sh >= 8) ? sh - 8 : 0;
            int nb  = 1 << (sh - nsh);
            for (int i = t; i < nb; i += NT) hist[i] = 0;
            __syncthreads();
            for (int i = t; i < NCOLS; i += NT) {
                uint32_t k = key_of(xb[i]);
                if (sh == 32 || (k >> sh) == P)
                    atomicAdd(&hist[(k >> nsh) & (nb - 1)], 1u);
            }
            __syncthreads();
            uint32_t hv = (t < nb) ? hist[t] : 0u;
            suffix_select(hv, scanb, sel, nb, R, t, lane, wid);
            P  = ((sh == 32) ? 0u : (P << (sh - nsh))) | sel[0];
            R -= sel[1];
            bc = sel[2];
            sh = nsh;
            __syncthreads();
        }
        const uint32_t kLo = (sh == 32) ? 0u : (P << sh);
        const uint32_t kHi = (sh == 32) ? 0xFFFFFFFFu
                             : (uint32_t)(((((uint64_t)P) + 1ull) << sh) - 1ull);
        if (t == 0) cnt[0] = 0;
        __syncthreads();
        for (int i = t; i < NCOLS; i += NT) {
            uint32_t k = key_of(xb[i]);
            if (k > kHi) {
                orow[i] = relu_of_key(k);       // definitely top-64
            } else if (k >= kLo) {
                uint32_t p = atomicAdd(&cnt[0], 1u);
                if (p < CAND_MAX) { ck[p] = k; ci[p] = (uint32_t)i; }
            }
        }
        __syncthreads();
        nc = cnt[0]; if (nc > CAND_MAX) nc = CAND_MAX;
        Pc = P; shc = sh; Rr = R;
    }

    // ---- exact threshold: 8-bit radix select over candidates ----
    while (shc > 0) {
        int nsh = (shc >= 8) ? shc - 8 : 0;
        int nb  = 1 << (shc - nsh);
        for (int i = t; i < nb; i += NT) hist[i] = 0;
        __syncthreads();
        for (uint32_t i = t; i < nc; i += NT) {
            uint32_t k = ck[i];
            if (shc == 32 || (k >> shc) == Pc)
                atomicAdd(&hist[(k >> nsh) & (nb - 1)], 1u);
        }
        __syncthreads();
        uint32_t hv = (t < nb) ? hist[t] : 0u;
        suffix_select(hv, scanb, sel, nb, Rr, t, lane, wid);
        Pc  = ((shc == 32) ? 0u : (Pc << (shc - nsh))) | sel[0];
        Rr -= sel[1];
        shc = nsh;
        __syncthreads();
    }
    const uint32_t Tkey   = Pc;
    const uint32_t keepEq = Rr;                 // # threshold-equal keys to keep
    const float    tval   = relu_of_key(Tkey);

    // ---- scatter strictly-above candidates; collect exact ties ----
    for (uint32_t i = t; i < nc; i += NT) {
        uint32_t k = ck[i];
        if (k > Tkey) {
            orow[ci[i]] = relu_of_key(k);
        } else if (k == Tkey) {
            uint32_t p = atomicAdd(&cnt[1], 1u);
            if (p < MAX_EQ) eqi[p] = ci[i];
        }
    }
    __syncthreads();

    // ---- ties: keep the keepEq equal-keys with smallest indices ----
    uint32_t ne = cnt[1];
    if (ne > MAX_EQ) ne = MAX_EQ;
    if (ne <= keepEq) {
        for (uint32_t e = t; e < ne; e += NT) orow[eqi[e]] = tval;
    } else {
        for (uint32_t e = t; e < ne; e += NT) {
            uint32_t idx = eqi[e];
            uint32_t c = 0;
            for (uint32_t j = 0; j < ne; j++) c += (eqi[j] < idx);
            if (c < keepEq) orow[idx] = tval;
        }
    }
}

extern "C" void kernel_launch(void* const* d_in, const int* in_sizes, int n_in,
                              void* d_out, int out_size) {
    const float* x = (const float*)d_in[0];
    float* out = (float*)d_out;
    const int rows = in_sizes[0] / NCOLS;

    cudaFuncSetAttribute(topk_relu_kernel,
                         cudaFuncAttributeMaxDynamicSharedMemorySize, SMEM_BYTES);
    topk_relu_kernel<<<rows, NT, SMEM_BYTES>>>(x, out);
}

// round 14
// speedup vs baseline: 1.5311x; 1.0301x over previous
#include <cuda_runtime.h>
#include <cstdint>

// Top-64 per row with ReLU, zeros elsewhere. One CTA per row, SINGLE fused
// data pass with 6-deep front-batched loads (6x LDG.128 then 6x STG.128
// zero-stores) and occupancy 3 CTAs/SM so the register budget (~42) allows
// all 6 loads to be simultaneously in flight (true MLP=6; the previous
// 4-CTA config clipped regs at 32 and re-serialized the batch).
// TCAND=2.6 -> ~114 candidates/row. Fast path: all-pairs rank epilogue
// (jax.lax.top_k tie semantics, lowest index wins). Radix select for nc>512;
// generic fallbacks keep correctness for any input distribution.

constexpr int NCOLS    = 24576;
constexpr int NT       = 512;              // 16 warps
constexpr int NW       = NT / 32;
constexpr int KSEL     = 64;
constexpr int VEC_IT   = NCOLS / (NT * 4); // 12 float4 per thread
constexpr int BATCH    = 6;                // 12 = 2 x 6
constexpr int CAND_MAX = 2048;
constexpr int MAX_EQ   = 128;
constexpr float TCAND  = 2.6f;

constexpr int SMEM_WORDS = 256 + 32 + 4 + 4 + NW + CAND_MAX + CAND_MAX + MAX_EQ;
constexpr int SMEM_BYTES = SMEM_WORDS * 4;

__device__ __forceinline__ uint32_t key_of(uint32_t b) {
    uint32_t mask = (uint32_t)((int32_t)b >> 31) | 0x80000000u;
    return b ^ mask;  // larger float <=> larger unsigned key
}
__device__ __forceinline__ float relu_of_key(uint32_t k) {
    return (k & 0x80000000u) ? __uint_as_float(k ^ 0x80000000u) : 0.0f;
}

__device__ __forceinline__ void collect4(
    const float4& v, int base, uint32_t* cnt, uint32_t* ck, uint32_t* ci)
{
    if (v.x > TCAND) { uint32_t p = atomicAdd(&cnt[0], 1u);
        if (p < CAND_MAX) { ck[p] = __float_as_uint(v.x) | 0x80000000u; ci[p] = base; } }
    if (v.y > TCAND) { uint32_t p = atomicAdd(&cnt[0], 1u);
        if (p < CAND_MAX) { ck[p] = __float_as_uint(v.y) | 0x80000000u; ci[p] = base + 1; } }
    if (v.z > TCAND) { uint32_t p = atomicAdd(&cnt[0], 1u);
        if (p < CAND_MAX) { ck[p] = __float_as_uint(v.z) | 0x80000000u; ci[p] = base + 2; } }
    if (v.w > TCAND) { uint32_t p = atomicAdd(&cnt[0], 1u);
        if (p < CAND_MAX) { ck[p] = __float_as_uint(v.w) | 0x80000000u; ci[p] = base + 3; } }
}

// suffix-select over nbins (<=256): thread t holds count v of bin t. Finds bin
// where suffix count crosses rank Kre. Writes sel={bin, strictly_above, count}.
__device__ __forceinline__ void suffix_select(
    uint32_t v, uint32_t* scanb, uint32_t* sel,
    int nbins, uint32_t Kre, int t, int lane, int wid)
{
    uint32_t s = v;  // inclusive suffix within warp
    #pragma unroll
    for (int off = 1; off < 32; off <<= 1) {
        uint32_t u = __shfl_down_sync(0xFFFFFFFFu, s, off);
        if (lane + off < 32) s += u;
    }
    const int nw = (nbins + 31) >> 5;
    if (lane == 0 && wid < nw) scanb[wid] = s;
    __syncthreads();
    if (t < 32) {
        uint32_t w = (t < nw) ? scanb[t] : 0u;
        uint32_t ws = w;
        #pragma unroll
        for (int off = 1; off < 32; off <<= 1) {
            uint32_t u = __shfl_down_sync(0xFFFFFFFFu, ws, off);
            if (t + off < 32) ws += u;
        }
        if (t < nw) scanb[t] = ws - w;   // exclusive suffix over warps above
    }
    __syncthreads();
    if (t < nbins) {
        uint32_t above = (s - v) + scanb[wid];
        if (above < Kre && above + v >= Kre) {
            sel[0] = (uint32_t)t; sel[1] = above; sel[2] = v;
        }
    }
    __syncthreads();
}

__global__ __launch_bounds__(NT, 3)
void topk_relu_kernel(const float* __restrict__ x, float* __restrict__ out) {
    extern __shared__ uint32_t smem[];
    uint32_t* hist  = smem;              // [256]
    uint32_t* scanb = hist + 256;        // [32]
    uint32_t* sel   = scanb + 32;        // [4]
    uint32_t* cnt   = sel + 4;           // [0]=cand, [1]=eq, [2]=npos
    uint32_t* wred  = cnt + 4;           // [NW]
    uint32_t* ck    = wred + NW;         // [CAND_MAX] candidate keys
    uint32_t* ci    = ck + CAND_MAX;     // [CAND_MAX] candidate indices
    uint32_t* eqi   = ci + CAND_MAX;     // [MAX_EQ]

    const int row  = blockIdx.x;
    const int t    = threadIdx.x;
    const int lane = t & 31;
    const int wid  = t >> 5;
    const float4* __restrict__ xv =
        reinterpret_cast<const float4*>(x + (size_t)row * NCOLS);
    float* __restrict__ orow = out + (size_t)row * NCOLS;
    float4* __restrict__ ov = reinterpret_cast<float4*>(orow);

    if (t == 0) { cnt[0] = 0; cnt[1] = 0; }
    __syncthreads();

    // ---- fused main pass: 6 front-batched loads, 6 zero-stores, collect ----
    const float4 z4 = make_float4(0.f, 0.f, 0.f, 0.f);
    #pragma unroll
    for (int it = 0; it < VEC_IT; it += BATCH) {
        float4 v[BATCH];
        int vi[BATCH];
        #pragma unroll
        for (int b = 0; b < BATCH; b++) {
            vi[b] = (it + b) * NT + t;
            v[b]  = __ldcs(xv + vi[b]);
        }
        #pragma unroll
        for (int b = 0; b < BATCH; b++)
            __stcs(ov + vi[b], z4);
        #pragma unroll
        for (int b = 0; b < BATCH; b++) {
            float m = fmaxf(fmaxf(v[b].x, v[b].y), fmaxf(v[b].z, v[b].w));
            if (m > TCAND) collect4(v[b], vi[b] * 4, cnt, ck, ci);
        }
    }
    __syncthreads();

    const uint32_t ncand = cnt[0];

    // ---- fast path A: rank epilogue (one thread per candidate) ----
    if (ncand >= KSEL && ncand <= (uint32_t)NT) {
        if (t < (int)ncand) {
            uint32_t myk = ck[t], myi = ci[t];
            uint32_t r = 0;
            for (uint32_t j = 0; j < ncand; j++) {
                uint32_t kj = ck[j];
                uint32_t ij = ci[j];
                r += (kj > myk) || (kj == myk && ij < myi);
            }
            if (r < KSEL) orow[myi] = relu_of_key(myk);
        }
        return;
    }

    uint32_t Pc, Rr, nc;
    int shc;
    if (ncand > (uint32_t)NT && ncand <= CAND_MAX) {
        // ---- fast path B: larger candidate set -> radix select ----
        Pc = 0; shc = 32; Rr = KSEL; nc = ncand;
    } else {
        // ---- rare paths: need the positive count (L2-resident re-read) ----
        uint32_t c0 = 0;
        #pragma unroll 4
        for (int it = 0; it < VEC_IT; it++) {
            float4 v = __ldcs(xv + it * NT + t);
            c0 += (v.x > 0.0f) + (v.y > 0.0f) + (v.z > 0.0f) + (v.w > 0.0f);
        }
        #pragma unroll
        for (int off = 16; off > 0; off >>= 1)
            c0 += __shfl_down_sync(0xFFFFFFFFu, c0, off);
        if (lane == 0) wred[wid] = c0;
        __syncthreads();
        if (t == 0) {
            uint32_t s = 0;
            #pragma unroll
            for (int w = 0; w < NW; w++) s += wred[w];
            cnt[2] = s;
        }
        __syncthreads();
        const uint32_t npos = cnt[2];

        if (npos < KSEL) {
            // 64th largest <= 0: output is exactly relu(x)
            #pragma unroll 4
            for (int it = 0; it < VEC_IT; it++) {
                int vi = it * NT + t;
                float4 v = __ldcs(xv + vi);
                v.x = fmaxf(v.x, 0.0f); v.y = fmaxf(v.y, 0.0f);
                v.z = fmaxf(v.z, 0.0f); v.w = fmaxf(v.w, 0.0f);
                __stcs(ov + vi, v);
            }
            return;
        }

        // generic fallback: key-space radix refine (any distribution)
        const uint32_t* xb = reinterpret_cast<const uint32_t*>(x) + (size_t)row * NCOLS;
        uint32_t P = 0, R = KSEL, bc = NCOLS;
        int sh = 32;
        while (bc > CAND_MAX && sh > 0) {
            int nsh = (sh >= 8) ? sh - 8 : 0;
            int nb  = 1 << (sh - nsh);
            for (int i = t; i < nb; i += NT) hist[i] = 0;
            __syncthreads();
            for (int i = t; i < NCOLS; i += NT) {
                uint32_t k = key_of(xb[i]);
                if (sh == 32 || (k >> sh) == P)
                    atomicAdd(&hist[(k >> nsh) & (nb - 1)], 1u);
            }
            __syncthreads();
            uint32_t hv = (t < nb) ? hist[t] : 0u;
            suffix_select(hv, scanb, sel, nb, R, t, lane, wid);
            P  = ((sh == 32) ? 0u : (P << (sh - nsh))) | sel[0];
            R -= sel[1];
            bc = sel[2];
            sh = nsh;
            __syncthreads();
        }
        const uint32_t kLo = (sh == 32) ? 0u : (P << sh);
        const uint32_t kHi = (sh == 32) ? 0xFFFFFFFFu
                             : (uint32_t)(((((uint64_t)P) + 1ull) << sh) - 1ull);
        if (t == 0) cnt[0] = 0;
        __syncthreads();
        for (int i = t; i < NCOLS; i += NT) {
            uint32_t k = key_of(xb[i]);
            if (k > kHi) {
                orow[i] = relu_of_key(k);       // definitely top-64
            } else if (k >= kLo) {
                uint32_t p = atomicAdd(&cnt[0], 1u);
                if (p < CAND_MAX) { ck[p] = k; ci[p] = (uint32_t)i; }
            }
        }
        __syncthreads();
        nc = cnt[0]; if (nc > CAND_MAX) nc = CAND_MAX;
        Pc = P; shc = sh; Rr = R;
    }

    // ---- exact threshold: 8-bit radix select over candidates ----
    while (shc > 0) {
        int nsh = (shc >= 8) ? shc - 8 : 0;
        int nb  = 1 << (shc - nsh);
        for (int i = t; i < nb; i += NT) hist[i] = 0;
        __syncthreads();
        for (uint32_t i = t; i < nc; i += NT) {
            uint32_t k = ck[i];
            if (shc == 32 || (k >> shc) == Pc)
                atomicAdd(&hist[(k >> nsh) & (nb - 1)], 1u);
        }
        __syncthreads();
        uint32_t hv = (t < nb) ? hist[t] : 0u;
        suffix_select(hv, scanb, sel, nb, Rr, t, lane, wid);
        Pc  = ((shc == 32) ? 0u : (Pc << (shc - nsh))) | sel[0];
        Rr -= sel[1];
        shc = nsh;
        __syncthreads();
    }
    const uint32_t Tkey   = Pc;
    const uint32_t keepEq = Rr;                 // # threshold-equal keys to keep
    const float    tval   = relu_of_key(Tkey);

    // ---- scatter strictly-above candidates; collect exact ties ----
    for (uint32_t i = t; i < nc; i += NT) {
        uint32_t k = ck[i];
        if (k > Tkey) {
            orow[ci[i]] = relu_of_key(k);
        } else if (k == Tkey) {
            uint32_t p = atomicAdd(&cnt[1], 1u);
            if (p < MAX_EQ) eqi[p] = ci[i];
        }
    }
    __syncthreads();

    // ---- ties: keep the keepEq equal-keys with smallest indices ----
    uint32_t ne = cnt[1];
    if (ne > MAX_EQ) ne = MAX_EQ;
    if (ne <= keepEq) {
        for (uint32_t e = t; e < ne; e += NT) orow[eqi[e]] = tval;
    } else {
        for (uint32_t e = t; e < ne; e += NT) {
            uint32_t idx = eqi[e];
            uint32_t c = 0;
            for (uint32_t j = 0; j < ne; j++) c += (eqi[j] < idx);
            if (c < keepEq) orow[idx] = tval;
        }
    }
}

extern "C" void kernel_launch(void* const* d_in, const int* in_sizes, int n_in,
                              void* d_out, int out_size) {
    const float* x = (const float*)d_in[0];
    float* out = (float*)d_out;
    const int rows = in_sizes[0] / NCOLS;

    cudaFuncSetAttribute(topk_relu_kernel,
                         cudaFuncAttributeMaxDynamicSharedMemorySize, SMEM_BYTES);
    topk_relu_kernel<<<rows, NT, SMEM_BYTES>>>(x, out);
}